// round 1
// baseline (speedup 1.0000x reference)
#include <cuda_runtime.h>
#include <cstdint>

#define BB 8
#define TT 2048
#define DD 256
#define HH 4
#define HDIM 64
#define NT (BB*TT)           // 16384 rows
#define NEGV (-1e9f)
#define EPSV 1e-5f
#define MQ 16                // queries per attention block
#define KBLK 256             // keys per score tile

// ---------------- device scratch (module-load allocated, not runtime) -------
__device__ float g_Q[BB*HH*TT*HDIM];
__device__ float g_K[BB*HH*TT*HDIM];
__device__ float g_V[BB*HH*TT*HDIM];
__device__ float g_attn[NT*DD];
__device__ unsigned char g_pad[NT];

// ---------------- mask dtype detection + expansion --------------------------
// key_padding_mask is a JAX bool; harness dtype may be uint8 / int32 / float32.
// Distinguish by byte patterns in the first 16384 bytes (safe under all interps):
//   float32 1.0f -> byte 0x3F at offsets 4i+3 ; int32 0/1 -> nonzero only at 4i ;
//   uint8 0/1   -> nonzeros at arbitrary offsets, never 0x3F.
__global__ void mask_prep_kernel(const void* __restrict__ maskraw) {
    __shared__ int cntOff, cnt3F, mode;
    const unsigned char* b = (const unsigned char*)maskraw;
    int tid = threadIdx.x;
    if (tid == 0) { cntOff = 0; cnt3F = 0; }
    __syncthreads();
    int lo = 0, l3 = 0;
    for (int i = tid; i < NT; i += blockDim.x) {
        unsigned char v = b[i];
        if ((i & 3) != 0 && v != 0) lo++;
        if ((i & 3) == 3 && v == 0x3F) l3++;
    }
    atomicAdd(&cntOff, lo);
    atomicAdd(&cnt3F, l3);
    __syncthreads();
    if (tid == 0) {
        if (cnt3F > 0) mode = 2;            // float32
        else if (cntOff > 0) mode = 0;      // uint8 / bool
        else mode = 1;                      // int32
    }
    __syncthreads();
    int m = mode;
    for (int i = tid; i < NT; i += blockDim.x) {
        unsigned char p;
        if (m == 0)      p = (b[i] != 0);
        else if (m == 1) p = (((const int*)maskraw)[i] != 0);
        else             p = (((const float*)maskraw)[i] != 0.0f);
        g_pad[i] = p;
    }
}

// ---------------- QKV projection: y = x @ W^T, scattered to (B,H,T,hd) ------
__global__ __launch_bounds__(256)
void qkv_proj_kernel(const float* __restrict__ x,
                     const float* __restrict__ Wq,
                     const float* __restrict__ Wk,
                     const float* __restrict__ Wv) {
    __shared__ float Xs[64][33];
    __shared__ float Ws[64][33];
    const float* W = (blockIdx.z == 0) ? Wq : (blockIdx.z == 1 ? Wk : Wv);
    float* O       = (blockIdx.z == 0) ? g_Q : (blockIdx.z == 1 ? g_K : g_V);
    int n0 = blockIdx.x * 64;
    int h  = blockIdx.y;          // j-tile == head (64 cols)
    int j0 = h * 64;
    int tid = threadIdx.x;
    int tx = tid & 15, ty = tid >> 4;

    float acc[4][4] = {};
    for (int kk = 0; kk < DD; kk += 32) {
        __syncthreads();
        #pragma unroll
        for (int t = 0; t < 2; t++) {
            int idx = tid * 2 + t;            // 0..511
            int r = idx >> 3, c4 = (idx & 7) * 4;
            float4 v = *(const float4*)&x[(n0 + r) * DD + kk + c4];
            Xs[r][c4] = v.x; Xs[r][c4+1] = v.y; Xs[r][c4+2] = v.z; Xs[r][c4+3] = v.w;
            float4 w = *(const float4*)&W[(j0 + r) * DD + kk + c4];
            Ws[r][c4] = w.x; Ws[r][c4+1] = w.y; Ws[r][c4+2] = w.z; Ws[r][c4+3] = w.w;
        }
        __syncthreads();
        #pragma unroll 8
        for (int k = 0; k < 32; k++) {
            float a[4], bv[4];
            #pragma unroll
            for (int i = 0; i < 4; i++) a[i]  = Xs[ty*4+i][k];
            #pragma unroll
            for (int j = 0; j < 4; j++) bv[j] = Ws[tx*4+j][k];
            #pragma unroll
            for (int i = 0; i < 4; i++)
                #pragma unroll
                for (int j = 0; j < 4; j++)
                    acc[i][j] += a[i] * bv[j];
        }
    }
    #pragma unroll
    for (int i = 0; i < 4; i++) {
        int n = n0 + ty * 4 + i;
        int bi = n >> 11, t = n & (TT - 1);
        float* orow = O + (((size_t)bi * HH + h) * TT + t) * HDIM + tx * 4;
        float4 v = make_float4(acc[i][0], acc[i][1], acc[i][2], acc[i][3]);
        *(float4*)orow = v;
    }
}

// ---------------- fused attention: scores -> sparsemax -> sparse AV ---------
// dyn smem layout (floats):
//  sQ   [0      .. 1024)     16 x 64 (pre-scaled Q)
//  sS   [1024   .. 33792)    16 x 2048 scores -> weights
//  sKVt [33792  .. 50432)    64 x 260 transposed K tile ; aliased by sIdx (p3/p4)
//  sMask 2048 B, sCnt 16 ints after
#define SMEM_ATTN_BYTES ((1024 + 32768 + 16640) * 4 + 2048 + 64)

__global__ __launch_bounds__(256)
void attn_kernel() {
    extern __shared__ unsigned char smraw[];
    float* sQ   = (float*)smraw;
    float* sS   = sQ + 1024;
    float* sKVt = sS + 32768;
    unsigned short* sIdx = (unsigned short*)sKVt;             // aliases sKVt
    unsigned char* sMask = (unsigned char*)(sKVt + 16640);
    int* sCnt = (int*)(sMask + 2048);

    int tid = threadIdx.x;
    int qt = blockIdx.x, h = blockIdx.y, b = blockIdx.z;
    int t0 = qt * MQ;
    const float* Qb = g_Q + (((size_t)b * HH + h) * TT) * HDIM;
    const float* Kb = g_K + (((size_t)b * HH + h) * TT) * HDIM;
    const float* Vb = g_V + (((size_t)b * HH + h) * TT) * HDIM;

    // ---- load Q tile, pre-scaled by 1/sqrt(hd) ----
    {
        int q = tid >> 4, d4 = (tid & 15) << 2;
        float4 v = *(const float4*)&Qb[(t0 + q) * HDIM + d4];
        const float inv = 0.125f;
        sQ[q * HDIM + d4 + 0] = v.x * inv;
        sQ[q * HDIM + d4 + 1] = v.y * inv;
        sQ[q * HDIM + d4 + 2] = v.z * inv;
        sQ[q * HDIM + d4 + 3] = v.w * inv;
    }
    for (int i = tid; i < TT; i += 256) sMask[i] = g_pad[b * TT + i];

    // ---- phase 2: scores S = Q' K^T ----
    int qg = tid >> 6;         // 0..3  -> 4 query rows each
    int kg = tid & 63;         // 0..63 -> 4 keys each
    for (int kb = 0; kb < TT; kb += KBLK) {
        __syncthreads();
        {   // load K tile transposed: sKVt[d][key]
            const float* Krow = Kb + (kb + tid) * HDIM;
            #pragma unroll
            for (int i = 0; i < 16; i++) {
                float4 v = *(const float4*)&Krow[i * 4];
                sKVt[(i*4+0) * 260 + tid] = v.x;
                sKVt[(i*4+1) * 260 + tid] = v.y;
                sKVt[(i*4+2) * 260 + tid] = v.z;
                sKVt[(i*4+3) * 260 + tid] = v.w;
            }
        }
        __syncthreads();
        float acc[4][4] = {};
        #pragma unroll 16
        for (int d = 0; d < HDIM; d++) {
            float4 kv = *(const float4*)&sKVt[d * 260 + kg * 4];
            float a0 = sQ[(qg*4+0) * HDIM + d];
            float a1 = sQ[(qg*4+1) * HDIM + d];
            float a2 = sQ[(qg*4+2) * HDIM + d];
            float a3 = sQ[(qg*4+3) * HDIM + d];
            acc[0][0] += a0*kv.x; acc[0][1] += a0*kv.y; acc[0][2] += a0*kv.z; acc[0][3] += a0*kv.w;
            acc[1][0] += a1*kv.x; acc[1][1] += a1*kv.y; acc[1][2] += a1*kv.z; acc[1][3] += a1*kv.w;
            acc[2][0] += a2*kv.x; acc[2][1] += a2*kv.y; acc[2][2] += a2*kv.z; acc[2][3] += a2*kv.w;
            acc[3][0] += a3*kv.x; acc[3][1] += a3*kv.y; acc[3][2] += a3*kv.z; acc[3][3] += a3*kv.w;
        }
        #pragma unroll
        for (int i = 0; i < 4; i++) {
            float4 v = make_float4(acc[i][0], acc[i][1], acc[i][2], acc[i][3]);
            *(float4*)&sS[(qg*4+i) * TT + kb + kg*4] = v;
        }
    }
    __syncthreads();

    // ---- phase 3: sparsemax per row (1 warp : 2 rows) ----
    int wid = tid >> 5, lane = tid & 31;
    for (int rr = 0; rr < 2; rr++) {
        int row = wid * 2 + rr;
        float z[64];
        float zmax = -3e38f;
        #pragma unroll
        for (int i = 0; i < 64; i++) {
            int k = i * 32 + lane;
            float v = sMask[k] ? NEGV : sS[row * TT + k];
            z[i] = v;
            zmax = fmaxf(zmax, v);
        }
        #pragma unroll
        for (int o = 16; o; o >>= 1) zmax = fmaxf(zmax, __shfl_xor_sync(0xffffffffu, zmax, o));
        // Newton fixed point: tau' = (sum_{z>tau} z - 1)/count, from tau0 = zmax-1
        float tau = zmax - 1.0f;
        for (int it = 0; it < 24; it++) {
            float s = 0.f, c = 0.f;
            #pragma unroll
            for (int i = 0; i < 64; i++) {
                if (z[i] > tau) { s += z[i]; c += 1.0f; }
            }
            #pragma unroll
            for (int o = 16; o; o >>= 1) {
                s += __shfl_xor_sync(0xffffffffu, s, o);
                c += __shfl_xor_sync(0xffffffffu, c, o);
            }
            float nt = (s - 1.0f) / c;
            if (nt == tau) break;
            tau = nt;
        }
        // write dense weights + compact nonzero index list (ballot scan)
        unsigned cnt = 0;
        #pragma unroll
        for (int i = 0; i < 64; i++) {
            float w = z[i] - tau;
            bool p = w > 0.f;
            sS[row * TT + i * 32 + lane] = p ? w : 0.f;
            unsigned m = __ballot_sync(0xffffffffu, p);
            if (p) {
                int pos = cnt + __popc(m & ((1u << lane) - 1u));
                sIdx[row * 2048 + pos] = (unsigned short)(i * 32 + lane);
            }
            cnt += __popc(m);
        }
        if (lane == 0) sCnt[row] = (int)cnt;
    }
    __syncthreads();

    // ---- phase 4: sparse A @ V (gather support rows of V from L2) ----
    {
        int q  = tid >> 4;         // 0..15
        int dg = tid & 15;         // 4 dims each
        int n = sCnt[q];
        float4 acc = make_float4(0.f, 0.f, 0.f, 0.f);
        for (int j = 0; j < n; j++) {
            int k = sIdx[q * 2048 + j];
            float w = sS[q * TT + k];
            float4 v = *(const float4*)&Vb[(size_t)k * HDIM + dg * 4];
            acc.x += w * v.x; acc.y += w * v.y; acc.z += w * v.z; acc.w += w * v.w;
        }
        *(float4*)&g_attn[((size_t)b * TT + t0 + q) * DD + h * HDIM + dg * 4] = acc;
    }
}

// ---------------- out-proj + residual + LayerNorm ---------------------------
__global__ __launch_bounds__(256)
void outproj_ln_kernel(const float* __restrict__ x,
                       const float* __restrict__ Wo,
                       const float* __restrict__ gamma,
                       const float* __restrict__ beta,
                       float* __restrict__ out) {
    __shared__ float sA[16][DD];
    __shared__ float sY[16][DD + 1];
    __shared__ float sMu[16], sRs[16];
    int n0 = blockIdx.x * 16;
    int tid = threadIdx.x;              // output column j

    for (int i = tid; i < 16 * 64; i += 256) {
        int r = i >> 6, c4 = (i & 63) * 4;
        *(float4*)&sA[r][c4] = *(const float4*)&g_attn[((size_t)n0 + r) * DD + c4];
    }
    __syncthreads();

    float acc[16] = {};
    const float* wrow = Wo + (size_t)tid * DD;
    for (int d = 0; d < DD; d += 4) {
        float4 w = *(const float4*)&wrow[d];
        #pragma unroll
        for (int r = 0; r < 16; r++) {
            acc[r] += w.x * sA[r][d] + w.y * sA[r][d+1]
                    + w.z * sA[r][d+2] + w.w * sA[r][d+3];
        }
    }
    #pragma unroll
    for (int r = 0; r < 16; r++)
        sY[r][tid] = acc[r] + x[((size_t)n0 + r) * DD + tid];
    __syncthreads();

    int wid = tid >> 5, lane = tid & 31;
    for (int rr = 0; rr < 2; rr++) {
        int r = wid * 2 + rr;
        float s = 0.f, s2 = 0.f;
        #pragma unroll
        for (int i = 0; i < 8; i++) {
            float v = sY[r][lane * 8 + i];
            s += v; s2 += v * v;
        }
        #pragma unroll
        for (int o = 16; o; o >>= 1) {
            s  += __shfl_xor_sync(0xffffffffu, s, o);
            s2 += __shfl_xor_sync(0xffffffffu, s2, o);
        }
        if (lane == 0) {
            float mu = s * (1.0f / DD);
            sMu[r] = mu;
            sRs[r] = rsqrtf(s2 * (1.0f / DD) - mu * mu + EPSV);
        }
    }
    __syncthreads();
    float g = gamma[tid], bt = beta[tid];
    #pragma unroll
    for (int r = 0; r < 16; r++)
        out[((size_t)n0 + r) * DD + tid] = (sY[r][tid] - sMu[r]) * sRs[r] * g + bt;
}

// ---------------- launch ----------------------------------------------------
extern "C" void kernel_launch(void* const* d_in, const int* in_sizes, int n_in,
                              void* d_out, int out_size) {
    const float* x     = (const float*)d_in[0];
    const void*  mask  = d_in[1];
    const float* Wq    = (const float*)d_in[2];
    const float* Wk    = (const float*)d_in[3];
    const float* Wv    = (const float*)d_in[4];
    const float* Wo    = (const float*)d_in[5];
    const float* gamma = (const float*)d_in[6];
    const float* beta  = (const float*)d_in[7];
    float* out = (float*)d_out;

    cudaFuncSetAttribute(attn_kernel, cudaFuncAttributeMaxDynamicSharedMemorySize,
                         SMEM_ATTN_BYTES);

    mask_prep_kernel<<<1, 256>>>(mask);
    qkv_proj_kernel<<<dim3(NT / 64, HH, 3), 256>>>(x, Wq, Wk, Wv);
    attn_kernel<<<dim3(TT / MQ, HH, BB), 256, SMEM_ATTN_BYTES>>>();
    outproj_ln_kernel<<<NT / 16, 256>>>(x, Wo, gamma, beta, out);
}

// round 2
// speedup vs baseline: 1.1559x; 1.1559x over previous
#include <cuda_runtime.h>
#include <cstdint>

#define BB 8
#define TT 2048
#define DD 256
#define HH 4
#define HDIM 64
#define NT (BB*TT)           // 16384 rows
#define NEGV (-1e9f)
#define EPSV 1e-5f
#define MQ 16                // queries per attention block
#define KBLK 256             // keys per score tile

// ---------------- device scratch -------------------------------------------
__device__ float g_Q[BB*HH*TT*HDIM];
__device__ float g_K[BB*HH*TT*HDIM];
__device__ float g_V[BB*HH*TT*HDIM];
__device__ float g_attn[NT*DD];
__device__ unsigned char g_pad[NT];

// ---------------- packed fp32x2 helpers -------------------------------------
union F2U { unsigned long long u; float2 f; };

__device__ __forceinline__ void ffma2(unsigned long long& acc,
                                      unsigned long long a, unsigned long long b) {
    asm("fma.rn.f32x2 %0, %1, %2, %0;" : "+l"(acc) : "l"(a), "l"(b));
}
__device__ __forceinline__ float hsum2(unsigned long long u) {
    F2U t; t.u = u; return t.f.x + t.f.y;
}

// ---------------- mask dtype detection + expansion --------------------------
__global__ void mask_prep_kernel(const void* __restrict__ maskraw) {
    __shared__ int cntOff, cnt3F, mode;
    const unsigned char* b = (const unsigned char*)maskraw;
    int tid = threadIdx.x;
    if (tid == 0) { cntOff = 0; cnt3F = 0; }
    __syncthreads();
    int lo = 0, l3 = 0;
    for (int i = tid; i < NT; i += blockDim.x) {
        unsigned char v = b[i];
        if ((i & 3) != 0 && v != 0) lo++;
        if ((i & 3) == 3 && v == 0x3F) l3++;
    }
    atomicAdd(&cntOff, lo);
    atomicAdd(&cnt3F, l3);
    __syncthreads();
    if (tid == 0) {
        if (cnt3F > 0) mode = 2;            // float32
        else if (cntOff > 0) mode = 0;      // uint8 / bool
        else mode = 1;                      // int32
    }
    __syncthreads();
    int m = mode;
    for (int i = tid; i < NT; i += blockDim.x) {
        unsigned char p;
        if (m == 0)      p = (b[i] != 0);
        else if (m == 1) p = (((const int*)maskraw)[i] != 0);
        else             p = (((const float*)maskraw)[i] != 0.0f);
        g_pad[i] = p;
    }
}

// ---------------- QKV projection: y = x @ W^T, scattered to (B,H,T,hd) ------
// 64n x 64j tile, k-tiles of 32. FMA2 packed along k. W smem XOR-swizzled for
// conflict-free 4-row-strided LDS.128 reads. Next tile prefetched in registers.
__global__ __launch_bounds__(256)
void qkv_proj_kernel(const float* __restrict__ x,
                     const float* __restrict__ Wq,
                     const float* __restrict__ Wk,
                     const float* __restrict__ Wv) {
    __shared__ float4 Xs4[512];   // 64 rows x 8 chunks
    __shared__ float4 Ws4[512];
    const float* W = (blockIdx.z == 0) ? Wq : (blockIdx.z == 1 ? Wk : Wv);
    float* O       = (blockIdx.z == 0) ? g_Q : (blockIdx.z == 1 ? g_K : g_V);
    int n0 = blockIdx.x * 64;
    int h  = blockIdx.y;
    int j0 = h * 64;
    int tid = threadIdx.x;
    int tx = tid & 15, ty = tid >> 4;

    // loader: this thread owns row lr, chunks lc, lc+1 of each 64x32 tile
    int f0 = tid * 2;
    int lr = f0 >> 3, lc = f0 & 7;
    int wxor = ((lr >> 2) & 7) ^ ((lr & 3) << 1);

    const float4* xg = (const float4*)&x[(size_t)(n0 + lr) * DD];
    const float4* wg = (const float4*)&W[(size_t)(j0 + lr) * DD];
    float4 px0 = xg[lc], px1 = xg[lc + 1];
    float4 pw0 = wg[lc], pw1 = wg[lc + 1];

    unsigned long long acc[4][4] = {};

    for (int kk = 0; kk < DD; kk += 32) {
        __syncthreads();
        Xs4[lr * 8 + lc]              = px0;
        Xs4[lr * 8 + lc + 1]          = px1;
        Ws4[lr * 8 + (lc ^ wxor)]     = pw0;
        Ws4[lr * 8 + ((lc + 1) ^ wxor)] = pw1;
        if (kk + 32 < DD) {
            int o = (kk + 32) >> 2;
            px0 = xg[o + lc]; px1 = xg[o + lc + 1];
            pw0 = wg[o + lc]; pw1 = wg[o + lc + 1];
        }
        __syncthreads();
        #pragma unroll
        for (int c = 0; c < 8; c++) {
            ulonglong2 xs[4], ws[4];
            #pragma unroll
            for (int i = 0; i < 4; i++)
                xs[i] = *(const ulonglong2*)&Xs4[(ty * 4 + i) * 8 + c];
            #pragma unroll
            for (int j = 0; j < 4; j++)
                ws[j] = *(const ulonglong2*)&Ws4[(tx * 4 + j) * 8 +
                                                 (c ^ (tx & 7) ^ (j << 1))];
            #pragma unroll
            for (int i = 0; i < 4; i++)
                #pragma unroll
                for (int j = 0; j < 4; j++) {
                    ffma2(acc[i][j], xs[i].x, ws[j].x);
                    ffma2(acc[i][j], xs[i].y, ws[j].y);
                }
        }
    }
    #pragma unroll
    for (int i = 0; i < 4; i++) {
        int n = n0 + ty * 4 + i;
        int bi = n >> 11, t = n & (TT - 1);
        float* orow = O + (((size_t)bi * HH + h) * TT + t) * HDIM + tx * 4;
        float4 v = make_float4(hsum2(acc[i][0]), hsum2(acc[i][1]),
                               hsum2(acc[i][2]), hsum2(acc[i][3]));
        *(float4*)orow = v;
    }
}

// ---------------- fused attention: scores -> sparsemax -> sparse AV ---------
// smem layout (floats):
//  sQ [0..1024)  16x64 (pre-scaled Q)
//  sS [1024..33792)  16x2048 scores -> weights
//  sK [33792..50176) 256x64 row-major K tile, XOR-swizzled; aliased by sIdx
//  then sMask 2048 B, sCnt 16 ints
#define SMEM_ATTN_BYTES ((1024 + 32768 + 16384) * 4 + 2048 + 64)

__global__ __launch_bounds__(256)
void attn_kernel() {
    extern __shared__ unsigned char smraw[];
    float* sQ = (float*)smraw;
    float* sS = sQ + 1024;
    float* sK = sS + 32768;
    float4* sK4 = (float4*)sK;
    unsigned short* sIdx = (unsigned short*)sK;         // aliases sK (64KB)
    unsigned char* sMask = (unsigned char*)(sK + 16384);
    int* sCnt = (int*)(sMask + 2048);

    int tid = threadIdx.x;
    int qt = blockIdx.x, h = blockIdx.y, b = blockIdx.z;
    int t0 = qt * MQ;
    const float* Qb = g_Q + (((size_t)b * HH + h) * TT) * HDIM;
    const float* Kb = g_K + (((size_t)b * HH + h) * TT) * HDIM;
    const float* Vb = g_V + (((size_t)b * HH + h) * TT) * HDIM;

    // ---- Q tile, pre-scaled by 1/sqrt(hd) ----
    {
        int q = tid >> 4, d4 = (tid & 15) << 2;
        float4 v = *(const float4*)&Qb[(t0 + q) * HDIM + d4];
        const float inv = 0.125f;
        sQ[q * HDIM + d4 + 0] = v.x * inv;
        sQ[q * HDIM + d4 + 1] = v.y * inv;
        sQ[q * HDIM + d4 + 2] = v.z * inv;
        sQ[q * HDIM + d4 + 3] = v.w * inv;
    }
    for (int i = tid; i < TT; i += 256) sMask[i] = g_pad[b * TT + i];

    // ---- phase 2: scores S = Q' K^T (FMA2, d-pair packed) ----
    int kg = tid & 63;         // 4 keys each
    int qg = tid >> 6;         // 4 query rows each
    int rx = ((tid >> 2) & 7) ^ ((tid & 3) << 1);
    const float4* Kg = (const float4*)Kb;

    float4 pre[16];
    {
        const float4* row = Kg + (size_t)tid * 16;
        #pragma unroll
        for (int c = 0; c < 16; c++) pre[c] = row[c];
    }

    for (int kb = 0; kb < TT; kb += KBLK) {
        __syncthreads();
        #pragma unroll
        for (int c = 0; c < 16; c++)
            sK4[tid * 16 + (c ^ rx)] = pre[c];
        if (kb + KBLK < TT) {
            const float4* row = Kg + (size_t)(kb + KBLK + tid) * 16;
            #pragma unroll
            for (int c = 0; c < 16; c++) pre[c] = row[c];
        }
        __syncthreads();

        unsigned long long acc[4][4] = {};
        #pragma unroll 4
        for (int c = 0; c < 16; c++) {
            ulonglong2 q[4];
            #pragma unroll
            for (int i = 0; i < 4; i++)
                q[i] = *(const ulonglong2*)&sQ[(qg * 4 + i) * HDIM + c * 4];
            #pragma unroll
            for (int j = 0; j < 4; j++) {
                ulonglong2 kv = *(const ulonglong2*)
                    &sK4[(kg * 4 + j) * 16 + (c ^ (kg & 7) ^ (j << 1))];
                #pragma unroll
                for (int i = 0; i < 4; i++) {
                    ffma2(acc[i][j], q[i].x, kv.x);
                    ffma2(acc[i][j], q[i].y, kv.y);
                }
            }
        }
        #pragma unroll
        for (int i = 0; i < 4; i++) {
            float4 v = make_float4(hsum2(acc[i][0]), hsum2(acc[i][1]),
                                   hsum2(acc[i][2]), hsum2(acc[i][3]));
            *(float4*)&sS[(qg * 4 + i) * TT + kb + kg * 4] = v;
        }
    }
    __syncthreads();

    // ---- phase 3: sparsemax per row (1 warp : 2 rows) ----
    int wid = tid >> 5, lane = tid & 31;
    for (int rr = 0; rr < 2; rr++) {
        int row = wid * 2 + rr;
        float z[64];
        float zmax = -3e38f;
        #pragma unroll
        for (int i = 0; i < 64; i++) {
            int k = i * 32 + lane;
            float v = sMask[k] ? NEGV : sS[row * TT + k];
            z[i] = v;
            zmax = fmaxf(zmax, v);
        }
        #pragma unroll
        for (int o = 16; o; o >>= 1) zmax = fmaxf(zmax, __shfl_xor_sync(0xffffffffu, zmax, o));
        float tau = zmax - 1.0f;
        for (int it = 0; it < 24; it++) {
            float s = 0.f, c = 0.f;
            #pragma unroll
            for (int i = 0; i < 64; i++) {
                if (z[i] > tau) { s += z[i]; c += 1.0f; }
            }
            #pragma unroll
            for (int o = 16; o; o >>= 1) {
                s += __shfl_xor_sync(0xffffffffu, s, o);
                c += __shfl_xor_sync(0xffffffffu, c, o);
            }
            float nt = (s - 1.0f) / c;
            if (nt == tau) break;
            tau = nt;
        }
        unsigned cnt = 0;
        #pragma unroll
        for (int i = 0; i < 64; i++) {
            float w = z[i] - tau;
            bool p = w > 0.f;
            sS[row * TT + i * 32 + lane] = p ? w : 0.f;
            unsigned m = __ballot_sync(0xffffffffu, p);
            if (p) {
                int pos = cnt + __popc(m & ((1u << lane) - 1u));
                sIdx[row * 2048 + pos] = (unsigned short)(i * 32 + lane);
            }
            cnt += __popc(m);
        }
        if (lane == 0) sCnt[row] = (int)cnt;
    }
    __syncthreads();

    // ---- phase 4: sparse A @ V ----
    {
        int q  = tid >> 4;
        int dg = tid & 15;
        int n = sCnt[q];
        float4 acc = make_float4(0.f, 0.f, 0.f, 0.f);
        int j = 0;
        for (; j + 2 <= n; j += 2) {
            int k0 = sIdx[q * 2048 + j];
            int k1 = sIdx[q * 2048 + j + 1];
            float w0 = sS[q * TT + k0];
            float w1 = sS[q * TT + k1];
            float4 v0 = *(const float4*)&Vb[(size_t)k0 * HDIM + dg * 4];
            float4 v1 = *(const float4*)&Vb[(size_t)k1 * HDIM + dg * 4];
            acc.x += w0 * v0.x + w1 * v1.x;
            acc.y += w0 * v0.y + w1 * v1.y;
            acc.z += w0 * v0.z + w1 * v1.z;
            acc.w += w0 * v0.w + w1 * v1.w;
        }
        if (j < n) {
            int k = sIdx[q * 2048 + j];
            float w = sS[q * TT + k];
            float4 v = *(const float4*)&Vb[(size_t)k * HDIM + dg * 4];
            acc.x += w * v.x; acc.y += w * v.y; acc.z += w * v.z; acc.w += w * v.w;
        }
        *(float4*)&g_attn[((size_t)b * TT + t0 + q) * DD + h * HDIM + dg * 4] = acc;
    }
}

// ---------------- out-proj + residual + LayerNorm ---------------------------
__global__ __launch_bounds__(256)
void outproj_ln_kernel(const float* __restrict__ x,
                       const float* __restrict__ Wo,
                       const float* __restrict__ gamma,
                       const float* __restrict__ beta,
                       float* __restrict__ out) {
    __shared__ float sA[16][DD];
    __shared__ float sY[16][DD + 1];
    __shared__ float sMu[16], sRs[16];
    int n0 = blockIdx.x * 16;
    int tid = threadIdx.x;              // output column j

    for (int i = tid; i < 16 * 64; i += 256) {
        int r = i >> 6, c4 = (i & 63) * 4;
        *(float4*)&sA[r][c4] = *(const float4*)&g_attn[((size_t)n0 + r) * DD + c4];
    }
    __syncthreads();

    unsigned long long acc2[16] = {};
    const ulonglong2* wrow = (const ulonglong2*)(Wo + (size_t)tid * DD);
    #pragma unroll 4
    for (int c = 0; c < 64; c++) {
        ulonglong2 w = wrow[c];
        #pragma unroll
        for (int r = 0; r < 16; r++) {
            ulonglong2 a = *(const ulonglong2*)&sA[r][c * 4];
            ffma2(acc2[r], w.x, a.x);
            ffma2(acc2[r], w.y, a.y);
        }
    }
    #pragma unroll
    for (int r = 0; r < 16; r++)
        sY[r][tid] = hsum2(acc2[r]) + x[((size_t)n0 + r) * DD + tid];
    __syncthreads();

    int wid = tid >> 5, lane = tid & 31;
    for (int rr = 0; rr < 2; rr++) {
        int r = wid * 2 + rr;
        float s = 0.f, s2 = 0.f;
        #pragma unroll
        for (int i = 0; i < 8; i++) {
            float v = sY[r][lane * 8 + i];
            s += v; s2 += v * v;
        }
        #pragma unroll
        for (int o = 16; o; o >>= 1) {
            s  += __shfl_xor_sync(0xffffffffu, s, o);
            s2 += __shfl_xor_sync(0xffffffffu, s2, o);
        }
        if (lane == 0) {
            float mu = s * (1.0f / DD);
            sMu[r] = mu;
            sRs[r] = rsqrtf(s2 * (1.0f / DD) - mu * mu + EPSV);
        }
    }
    __syncthreads();
    float g = gamma[tid], bt = beta[tid];
    #pragma unroll
    for (int r = 0; r < 16; r++)
        out[((size_t)n0 + r) * DD + tid] = (sY[r][tid] - sMu[r]) * sRs[r] * g + bt;
}

// ---------------- launch ----------------------------------------------------
extern "C" void kernel_launch(void* const* d_in, const int* in_sizes, int n_in,
                              void* d_out, int out_size) {
    const float* x     = (const float*)d_in[0];
    const void*  mask  = d_in[1];
    const float* Wq    = (const float*)d_in[2];
    const float* Wk    = (const float*)d_in[3];
    const float* Wv    = (const float*)d_in[4];
    const float* Wo    = (const float*)d_in[5];
    const float* gamma = (const float*)d_in[6];
    const float* beta  = (const float*)d_in[7];
    float* out = (float*)d_out;

    cudaFuncSetAttribute(attn_kernel, cudaFuncAttributeMaxDynamicSharedMemorySize,
                         SMEM_ATTN_BYTES);

    mask_prep_kernel<<<1, 256>>>(mask);
    qkv_proj_kernel<<<dim3(NT / 64, HH, 3), 256>>>(x, Wq, Wk, Wv);
    attn_kernel<<<dim3(TT / MQ, HH, BB), 256, SMEM_ATTN_BYTES>>>();
    outproj_ln_kernel<<<NT / 16, 256>>>(x, Wo, gamma, beta, out);
}